// round 15
// baseline (speedup 1.0000x reference)
#include <cuda_runtime.h>

// SigKerMMD with triangle symmetry (work = 2080 + 4096 + 2080 = 8256 pairs).
// out = (sum_XX - 2*sum_XY + sum_YY) / 4096
//
// R15 = R14 resubmit (R14 hit an infra-level container failure, same as
// R7/R12, both of which passed verbatim on resubmit).
// R14 theory: TLP doubling with the lean gram. Evidence R10-R13: issue-slot
// total is constant and time is pinned at ~33us by latency at 3.5 warps/SMSP;
// instruction/ILP tweaks are flat. So trade +18% PDE instructions for 2x
// warps: 16-lane wavefront groups, 4 cols/thread, 2 pairs/warp -> 4128
// warps, 1032 blocks (~7/SM, balanced), occ ~42%.

#define SEQ 32
#define CH 5
#define SEQCH (SEQ * CH)          // 160
#define NTRI 2080                 // 64*65/2
#define NPAIRS (NTRI + 4096 + NTRI)          // 8256
#define PAIRS_PER_WARP 2
#define NWARPS (NPAIRS / PAIRS_PER_WARP)     // 4128
#define WARPS_PER_BLOCK 4
#define NBLOCKS (NWARPS / WARPS_PER_BLOCK)   // 1032
#define THREADS_PER_BLOCK (WARPS_PER_BLOCK * 32)

#define AA_RP 31
#define AA_STRIDE (AA_RP * 32)    // 992 floats (3968B, 8B-aligned) per pair

__device__ float g_aa[(size_t)NPAIRS * AA_STRIDE];   // ~32.8 MB staging (L2)
__device__ float g_block[NBLOCKS];
__device__ unsigned int g_done = 0;

// decode work item -> (seg, a, b, weight). Layout:
//   [0, 2080)      XX upper triangle (a<=b), weight 2 off-diag / 1 diag
//   [2080, 6176)   XY full, weight -2
//   [6176, 8256)   YY upper triangle, weight 2 off-diag / 1 diag
__device__ __forceinline__ void decode_pair(int w, int& seg, int& a, int& b, float& wgt)
{
    if (w < NTRI) {
        seg = 0;
        int t = w;
        int ar = (int)((129.0f - sqrtf(16641.0f - 8.0f * (float)t)) * 0.5f);
        if (ar < 0) ar = 0;
        while (ar > 0 && (ar * 64 - (ar * (ar - 1)) / 2) > t) ar--;
        while (((ar + 1) * 64 - ((ar + 1) * ar) / 2) <= t) ar++;
        a = ar;
        b = ar + (t - (ar * 64 - (ar * (ar - 1)) / 2));
        wgt = (a == b) ? 1.0f : 2.0f;
    } else if (w < NTRI + 4096) {
        seg = 1;
        int p = w - NTRI;
        a = p >> 6;
        b = p & 63;
        wgt = -2.0f;
    } else {
        seg = 2;
        int t = w - (NTRI + 4096);
        int ar = (int)((129.0f - sqrtf(16641.0f - 8.0f * (float)t)) * 0.5f);
        if (ar < 0) ar = 0;
        while (ar > 0 && (ar * 64 - (ar * (ar - 1)) / 2) > t) ar--;
        while (((ar + 1) * 64 - ((ar + 1) * ar) / 2) <= t) ar++;
        a = ar;
        b = ar + (t - (ar * 64 - (ar * (ar - 1)) / 2));
        wgt = (a == b) ? 1.0f : 2.0f;
    }
}

__global__ __launch_bounds__(THREADS_PER_BLOCK)
void sig_kernel(const float* __restrict__ x,
                const float* __restrict__ y,
                const float* __restrict__ sig,
                float* __restrict__ out)
{
    // padded A rows: [m][0..4] = mu_a values, [5] = |mu_a|^2, [6..7] pad
    __shared__ float sh_xa[WARPS_PER_BLOCK][SEQ][8];
    __shared__ float sh_res[WARPS_PER_BLOCK];
    __shared__ int   sh_last;
    __shared__ float sh_red[THREADS_PER_BLOCK];

    const int warp = threadIdx.x >> 5;
    const int lane = threadIdx.x & 31;
    const int wg   = blockIdx.x * WARPS_PER_BLOCK + warp;  // warp id 0..4127

    // channel scales for mu = [x0, x1*s0, x2*s1, x3*s2, x4*s3]
    float cs[CH];
    cs[0] = 1.0f;
    cs[1] = sig[0]; cs[2] = sig[1]; cs[3] = sig[2]; cs[4] = sig[3];

    // ======== Phase A: gram + dyadic increments for 2 pairs (full warp) ========
    int prevKey = -1;
    #pragma unroll 1
    for (int g = 0; g < PAIRS_PER_WARP; g++) {
        const int w = wg * PAIRS_PER_WARP + g;    // work item 0..8255
        int seg, a, b; float wdummy;
        decode_pair(w, seg, a, b, wdummy);

        const float* Aptr = ((seg < 2) ? x : y) + a * SEQCH;
        const bool   Ascale = (seg < 2);
        const float* Bptr = ((seg == 0) ? x : y) + b * SEQCH;
        const bool   Bscale = (seg == 0);

        // load A sequence (sigma-scaled if from x) into padded shared + norms;
        // skip when this warp already has the same A block staged
        const int key = Ascale ? a : 64 + a;
        if (key != prevKey) {
            prevKey = key;
            #pragma unroll
            for (int idx = lane; idx < SEQCH; idx += 32) {
                int row = idx / CH;
                int c   = idx - row * CH;
                float v = Aptr[idx];
                if (Ascale) v *= cs[c];
                sh_xa[warp][row][c] = v;
            }
            __syncwarp();
            {
                float4 lo = *reinterpret_cast<const float4*>(&sh_xa[warp][lane][0]);
                float  h4 = sh_xa[warp][lane][4];
                float  s  = lo.x * lo.x + lo.y * lo.y + lo.z * lo.z
                          + lo.w * lo.w + h4 * h4;
                sh_xa[warp][lane][5] = s;
            }
            __syncwarp();
        }

        // B column (lane n): yb pre-scaled by -2 so d2 = (xn+yn) + sum(ybm*xa)
        float ybm[CH];
        float yn = 0.0f;
        #pragma unroll
        for (int c = 0; c < CH; c++) {
            float v = Bptr[lane * CH + c];
            if (Bscale) v *= cs[c];
            yn += v * v;
            ybm[c] = -2.0f * v;
        }

        // gram column + second differences -> aa (fp32) to global staging
        float* aout = g_aa + (size_t)w * AA_STRIDE + lane;
        const float* xrow = &sh_xa[warp][0][0];
        float gprev = 0.0f;
        #pragma unroll 4
        for (int m = 0; m < SEQ; m++) {
            float4 lo = *reinterpret_cast<const float4*>(xrow);
            float2 hi = *reinterpret_cast<const float2*>(xrow + 4);
            xrow += 8;
            float d2 = hi.y + yn;                 // xn + yn
            d2 = fmaf(ybm[0], lo.x, d2);
            d2 = fmaf(ybm[1], lo.y, d2);
            d2 = fmaf(ybm[2], lo.z, d2);
            d2 = fmaf(ybm[3], lo.w, d2);
            d2 = fmaf(ybm[4], hi.x, d2);
            float gv = __expf(-d2);               // RBF_SIGMA = 1.0
            if (m > 0) {
                float cd  = gv - gprev;
                float cdn = __shfl_down_sync(0xffffffffu, cd, 1);
                float aa = (lane < 31) ? (cdn - cd) * 0.25f : 0.0f;
                *aout = aa;
                aout += 32;
            }
            gprev = gv;
        }
        __syncwarp();
    }

    // make this warp's aa stores visible to its own cross-lane reads
    __threadfence_block();
    __syncwarp();

    // ======== Phase B: wavefront PDE (16-lane group per pair, 4 cols/thr) ====
    // K is (63x63) per pair, K[0][*]=K[*][0]=1.
    // K[i][j] = (K[i][j-1]+K[i-1][j])*c1 - K[i-1][j-1]*c2
    //   n_j = c1_j*n_{j-1} + b_j,  b_j = c1_j*k_j - c2_j*k_{j-1}
    // thread t owns cols 4t+1..4t+4; step s computes row i = s - t + 1;
    // 77 steps. Body runs UNCONDITIONALLY (coeffs==1 & inL==inD => identity;
    // stale-coeff drain garbage never reaches t=15's k2 before readout —
    // proven in R13). Only the coefficient load keeps the r<62&&even guard.
    const int grp = lane >> 4;                   // group within warp (0..1)
    const int t   = lane & 15;                   // wavefront thread (0..15)
    const int pair = wg * PAIRS_PER_WARP + grp;  // work item of this group

    int segp, ap_, bp_; float wgt;
    decode_pair(pair, segp, ap_, bp_, wgt);

    // thread t reads colpairs 2t,2t+1 = float2 at offset t; row-pair stride 16
    const float2* ap = reinterpret_cast<const float2*>(
                           g_aa + (size_t)pair * AA_STRIDE) + t;

    // prefetch ring: cur = next row-pair to consume
    float2 cur = ap[0];
    float2 nxt = ap[16];
    float2 nx2 = ap[32];
    ap += 48;
    int remaining = 31 - 3;   // row-pair loads left after preloads

    float k1 = 1.0f, k2 = 1.0f, k3 = 1.0f, k4 = 1.0f;
    float inL = 1.0f;
    float inD = 1.0f;
    float c1a = 1.0f, c2a = 1.0f, c1b = 1.0f, c2b = 1.0f;

    #pragma unroll 4
    for (int s = 0; s < 77; s++) {
        unsigned r = (unsigned)(s - t);                    // i-1
        if (r < 62u && !(r & 1u)) {                        // new row-pair coeffs
            float q;
            q = cur.x * cur.x * (1.0f / 12.0f);
            c1a = 1.0f + 0.5f * cur.x + q;  c2a = 1.0f - q;
            q = cur.y * cur.y * (1.0f / 12.0f);
            c1b = 1.0f + 0.5f * cur.y + q;  c2b = 1.0f - q;
            cur = nxt; nxt = nx2;
            if (remaining > 0) {                            // stay in-bounds
                nx2 = *ap; ap += 16; remaining--;
            }
        }
        // parallel b_j (independent of the serial chain)
        float b1 = fmaf(c1a, k1, -c2a * inD);
        float b2 = fmaf(c1a, k2, -c2a * k1);
        float b3 = fmaf(c1b, k3, -c2b * k2);
        float b4 = fmaf(c1b, k4, -c2b * k3);
        // serial chain: 4 single FFMAs
        k1 = fmaf(c1a, inL, b1);
        k2 = fmaf(c1a, k1,  b2);
        k3 = fmaf(c1b, k2,  b3);
        k4 = fmaf(c1b, k3,  b4);

        inD = inL;
        // shuffle for the NEXT step, issued as soon as k4 is ready
        inL = __shfl_up_sync(0xffffffffu, k4, 1, 16);      // K[i+1][4t] from t-1
        if (t == 0) inL = 1.0f;                            // left boundary
    }

    // thread t=15 owns cols 61..64 -> k2 = K[62][62]
    float v = (t == 15) ? (wgt * k2) : 0.0f;
    // deterministic warp butterfly sum (fixed shuffle sequence)
    #pragma unroll
    for (int off = 16; off > 0; off >>= 1)
        v += __shfl_xor_sync(0xffffffffu, v, off);
    if (lane == 0) sh_res[warp] = v;
    __syncthreads();

    // ======== publish block partial + last-block fixed-order reduction ========
    if (threadIdx.x == 0) {
        g_block[blockIdx.x] = (sh_res[0] + sh_res[1]) + (sh_res[2] + sh_res[3]);
        __threadfence();
        unsigned tt = atomicAdd(&g_done, 1u);
        sh_last = (tt == NBLOCKS - 1);
    }
    __syncthreads();

    if (sh_last) {
        float s = 0.0f;
        #pragma unroll 1
        for (int i = threadIdx.x; i < NBLOCKS; i += THREADS_PER_BLOCK)
            s += g_block[i];
        sh_red[threadIdx.x] = s;
        __syncthreads();
        #pragma unroll
        for (int off = THREADS_PER_BLOCK / 2; off > 0; off >>= 1) {
            if (threadIdx.x < off) sh_red[threadIdx.x] += sh_red[threadIdx.x + off];
            __syncthreads();
        }
        if (threadIdx.x == 0) {
            out[0] = sh_red[0] * (1.0f / 4096.0f);
            g_done = 0;   // reset for next graph replay
        }
    }
}

extern "C" void kernel_launch(void* const* d_in, const int* in_sizes, int n_in,
                              void* d_out, int out_size)
{
    // Expected order: x [64*32*5], y [64*32*5], sigma_param [4].
    const float* x = nullptr;
    const float* yy = nullptr;
    const float* sp = nullptr;
    for (int i = 0; i < n_in; i++) {
        if (in_sizes[i] == CH - 1) { sp = (const float*)d_in[i]; }
        else if (!x)               { x  = (const float*)d_in[i]; }
        else if (!yy)              { yy = (const float*)d_in[i]; }
    }

    sig_kernel<<<NBLOCKS, THREADS_PER_BLOCK>>>(x, yy, sp, (float*)d_out);
}

// round 16
// speedup vs baseline: 1.0035x; 1.0035x over previous
#include <cuda_runtime.h>

// SigKerMMD with triangle symmetry (work = 2080 + 4096 + 2080 = 8256 pairs).
// out = (sum_XX - 2*sum_XY + sum_YY) / 4096
//
// R16 = R10 best-measured kernel (8-lane wavefront groups, 4 pairs/warp,
// 2064 warps, b-split chain, bottom shuffle) with ONE mechanism-targeted fix:
// the coefficient block is per-lane divergent (parity of r = s-t), so its ring
// MOVs + bounds logic issue as both-path predicated work every step. Replaced
// the 3-deep mov-ring with a 2-deep ring refilled by a single CLAMPED direct
// load from a zero-padded aa row-pair (aa=0 -> c1=c2=1 -> identity), deleting
// the nx2 moves and `remaining` bookkeeping entirely.

#define SEQ 32
#define CH 5
#define SEQCH (SEQ * CH)          // 160
#define NTRI 2080                 // 64*65/2
#define NPAIRS (NTRI + 4096 + NTRI)          // 8256
#define PAIRS_PER_WARP 4
#define NWARPS (NPAIRS / PAIRS_PER_WARP)     // 2064
#define WARPS_PER_BLOCK 4
#define NBLOCKS (NWARPS / WARPS_PER_BLOCK)   // 516
#define THREADS_PER_BLOCK (WARPS_PER_BLOCK * 32)

#define AA_RP 32                  // 31 real row-pairs + 1 ZERO pad (identity)
#define AA_STRIDE (AA_RP * 32)    // 1024 floats (4096B) per pair

__device__ float g_aa[(size_t)NPAIRS * AA_STRIDE];   // ~33.8 MB staging (L2)
__device__ float g_block[NBLOCKS];
__device__ unsigned int g_done = 0;

// decode work item -> (seg, a, b, weight). Layout:
//   [0, 2080)      XX upper triangle (a<=b), weight 2 off-diag / 1 diag
//   [2080, 6176)   XY full, weight -2
//   [6176, 8256)   YY upper triangle, weight 2 off-diag / 1 diag
__device__ __forceinline__ void decode_pair(int w, int& seg, int& a, int& b, float& wgt)
{
    if (w < NTRI) {
        seg = 0;
        int t = w;
        int ar = (int)((129.0f - sqrtf(16641.0f - 8.0f * (float)t)) * 0.5f);
        if (ar < 0) ar = 0;
        while (ar > 0 && (ar * 64 - (ar * (ar - 1)) / 2) > t) ar--;
        while (((ar + 1) * 64 - ((ar + 1) * ar) / 2) <= t) ar++;
        a = ar;
        b = ar + (t - (ar * 64 - (ar * (ar - 1)) / 2));
        wgt = (a == b) ? 1.0f : 2.0f;
    } else if (w < NTRI + 4096) {
        seg = 1;
        int p = w - NTRI;
        a = p >> 6;
        b = p & 63;
        wgt = -2.0f;
    } else {
        seg = 2;
        int t = w - (NTRI + 4096);
        int ar = (int)((129.0f - sqrtf(16641.0f - 8.0f * (float)t)) * 0.5f);
        if (ar < 0) ar = 0;
        while (ar > 0 && (ar * 64 - (ar * (ar - 1)) / 2) > t) ar--;
        while (((ar + 1) * 64 - ((ar + 1) * ar) / 2) <= t) ar++;
        a = ar;
        b = ar + (t - (ar * 64 - (ar * (ar - 1)) / 2));
        wgt = (a == b) ? 1.0f : 2.0f;
    }
}

__global__ __launch_bounds__(THREADS_PER_BLOCK)
void sig_kernel(const float* __restrict__ x,
                const float* __restrict__ y,
                const float* __restrict__ sig,
                float* __restrict__ out)
{
    __shared__ float sh_xa[WARPS_PER_BLOCK][SEQCH];
    __shared__ float sh_xn[WARPS_PER_BLOCK][SEQ];
    __shared__ float sh_res[WARPS_PER_BLOCK][PAIRS_PER_WARP];
    __shared__ int   sh_last;
    __shared__ float sh_red[THREADS_PER_BLOCK];

    const int warp = threadIdx.x >> 5;
    const int lane = threadIdx.x & 31;
    const int wg   = blockIdx.x * WARPS_PER_BLOCK + warp;  // warp id 0..2063

    // channel scales for mu = [x0, x1*s0, x2*s1, x3*s2, x4*s3]
    float cs[CH];
    cs[0] = 1.0f;
    cs[1] = sig[0]; cs[2] = sig[1]; cs[3] = sig[2]; cs[4] = sig[3];

    // ======== Phase A: gram + dyadic increments for 4 pairs (full warp) ========
    #pragma unroll 1
    for (int g = 0; g < PAIRS_PER_WARP; g++) {
        const int w = wg * PAIRS_PER_WARP + g;    // work item 0..8255
        int seg, a, b; float wdummy;
        decode_pair(w, seg, a, b, wdummy);

        const float* Aptr = ((seg < 2) ? x : y) + a * SEQCH;
        const bool   Ascale = (seg < 2);
        const float* Bptr = ((seg == 0) ? x : y) + b * SEQCH;
        const bool   Bscale = (seg == 0);

        // load A sequence (possibly sigma-scaled) into shared
        #pragma unroll
        for (int idx = lane; idx < SEQCH; idx += 32) {
            float v = Aptr[idx];
            if (Ascale) v *= cs[idx % CH];
            sh_xa[warp][idx] = v;
        }
        __syncwarp();

        // per-row squared norms of A
        {
            float s = 0.0f;
            #pragma unroll
            for (int c = 0; c < CH; c++) {
                float v = sh_xa[warp][lane * CH + c];
                s += v * v;
            }
            sh_xn[warp][lane] = s;
        }

        // B column (lane n) into registers
        float yb[CH];
        float yn = 0.0f;
        #pragma unroll
        for (int c = 0; c < CH; c++) {
            float v = Bptr[lane * CH + c];
            if (Bscale) v *= cs[c];
            yb[c] = v;
            yn += v * v;
        }
        __syncwarp();

        // gram column + second differences -> aa (fp32) to global staging
        float* aout = g_aa + (size_t)w * AA_STRIDE + lane;
        float gprev = 0.0f;
        #pragma unroll 4
        for (int m = 0; m < SEQ; m++) {
            float dot = 0.0f;
            #pragma unroll
            for (int c = 0; c < CH; c++)
                dot = fmaf(sh_xa[warp][m * CH + c], yb[c], dot);
            float d2 = sh_xn[warp][m] + yn - 2.0f * dot;
            float gv = __expf(-d2);         // RBF_SIGMA = 1.0
            if (m > 0) {
                float cd  = gv - gprev;
                float cdn = __shfl_down_sync(0xffffffffu, cd, 1);
                float aa = (lane < 31) ? (cdn - cd) * 0.25f : 0.0f;
                *aout = aa;
                aout += 32;
            }
            gprev = gv;
        }
        // zero pad row-pair 31: aa=0 => c1=c2=1 => identity update
        *aout = 0.0f;
        __syncwarp();
    }

    // make this warp's aa stores visible to its own cross-lane reads
    __threadfence_block();
    __syncwarp();

    // ======== Phase B: wavefront PDE (8-lane group per pair) ========
    // K is (63x63) per pair, K[0][*]=K[*][0]=1.
    // K[i][j] = (K[i][j-1]+K[i-1][j])*c1 - K[i-1][j-1]*c2
    //   n_j = c1_j*n_{j-1} + b_j,  b_j = c1_j*k_j - c2_j*k_{j-1}
    // thread t owns cols 8t+1..8t+8; step s computes row i = s - t + 1.
    // inD (= K[i-1][8t]) equals previous step's inL; shuffle issued at loop
    // bottom so its latency overlaps the next step's b computations.
    // aa streamed via 2-deep ring; refill = single clamped load (pad rp=31
    // is zeros), no nx2 moves, no `remaining` bookkeeping.
    const int grp = lane >> 3;                   // pair within warp (0..3)
    const int t   = lane & 7;                    // wavefront thread (0..7)
    const int pair = wg * PAIRS_PER_WARP + grp;  // work item of this group

    int segp, ap_, bp_; float wgt;
    decode_pair(pair, segp, ap_, bp_, wgt);

    const float4* base4 = reinterpret_cast<const float4*>(
                              g_aa + (size_t)pair * AA_STRIDE) + t;

    // 2-deep prefetch ring: cur = next row-pair to consume, nxt = one ahead
    float4 cur = base4[0];        // row-pair 0
    float4 nxt = base4[8];        // row-pair 1

    float k1 = 1.0f, k2 = 1.0f, k3 = 1.0f, k4 = 1.0f;
    float k5 = 1.0f, k6 = 1.0f, k7 = 1.0f, k8 = 1.0f;
    float inL = 1.0f;
    float inD = 1.0f;
    float c1a = 1.0f, c2a = 1.0f, c1b = 1.0f, c2b = 1.0f;
    float c1c = 1.0f, c2c = 1.0f, c1d = 1.0f, c2d = 1.0f;

    #pragma unroll 2
    for (int s = 0; s < 69; s++) {
        unsigned r = (unsigned)(s - t);                    // i-1
        if (r < 62u) {
            if (!(r & 1u)) {                               // new row-pair coeffs
                float q;
                q = cur.x * cur.x * (1.0f / 12.0f);
                c1a = 1.0f + 0.5f * cur.x + q;  c2a = 1.0f - q;
                q = cur.y * cur.y * (1.0f / 12.0f);
                c1b = 1.0f + 0.5f * cur.y + q;  c2b = 1.0f - q;
                q = cur.z * cur.z * (1.0f / 12.0f);
                c1c = 1.0f + 0.5f * cur.z + q;  c2c = 1.0f - q;
                q = cur.w * cur.w * (1.0f / 12.0f);
                c1d = 1.0f + 0.5f * cur.w + q;  c2d = 1.0f - q;
                cur = nxt;
                // refill one ahead: row-pair u+2, clamped into the zero pad
                unsigned nrp = (r >> 1) + 2u;
                nxt = base4[(nrp < 31u ? nrp : 31u) * 8];
            }
            // parallel b_j (independent of the serial chain)
            float b1 = fmaf(c1a, k1, -c2a * inD);
            float b2 = fmaf(c1a, k2, -c2a * k1);
            float b3 = fmaf(c1b, k3, -c2b * k2);
            float b4 = fmaf(c1b, k4, -c2b * k3);
            float b5 = fmaf(c1c, k5, -c2c * k4);
            float b6 = fmaf(c1c, k6, -c2c * k5);
            float b7 = fmaf(c1d, k7, -c2d * k6);
            float b8 = fmaf(c1d, k8, -c2d * k7);
            // serial chain: 8 single FFMAs
            k1 = fmaf(c1a, inL, b1);
            k2 = fmaf(c1a, k1,  b2);
            k3 = fmaf(c1b, k2,  b3);
            k4 = fmaf(c1b, k3,  b4);
            k5 = fmaf(c1c, k4,  b5);
            k6 = fmaf(c1c, k5,  b6);
            k7 = fmaf(c1d, k6,  b7);
            k8 = fmaf(c1d, k7,  b8);
        }
        inD = inL;
        // shuffle for the NEXT step, issued as soon as k8 is ready
        inL = __shfl_up_sync(0xffffffffu, k8, 1, 8);       // K[i+1][8t] from t-1
        if (t == 0) inL = 1.0f;                            // left boundary
    }

    // thread t=7 owns cols 57..64 -> k6 = K[62][62]
    if (t == 7)
        sh_res[warp][grp] = wgt * k6;
    __syncthreads();

    // ======== publish block partial + last-block fixed-order reduction ========
    if (threadIdx.x == 0) {
        float bsum = 0.0f;
        #pragma unroll
        for (int ww = 0; ww < WARPS_PER_BLOCK; ww++)
            bsum += (sh_res[ww][0] + sh_res[ww][1]) + (sh_res[ww][2] + sh_res[ww][3]);
        g_block[blockIdx.x] = bsum;
        __threadfence();
        unsigned tt = atomicAdd(&g_done, 1u);
        sh_last = (tt == NBLOCKS - 1);
    }
    __syncthreads();

    if (sh_last) {
        float s = 0.0f;
        #pragma unroll 1
        for (int i = threadIdx.x; i < NBLOCKS; i += THREADS_PER_BLOCK)
            s += g_block[i];
        sh_red[threadIdx.x] = s;
        __syncthreads();
        #pragma unroll
        for (int off = THREADS_PER_BLOCK / 2; off > 0; off >>= 1) {
            if (threadIdx.x < off) sh_red[threadIdx.x] += sh_red[threadIdx.x + off];
            __syncthreads();
        }
        if (threadIdx.x == 0) {
            out[0] = sh_red[0] * (1.0f / 4096.0f);
            g_done = 0;   // reset for next graph replay
        }
    }
}

extern "C" void kernel_launch(void* const* d_in, const int* in_sizes, int n_in,
                              void* d_out, int out_size)
{
    // Expected order: x [64*32*5], y [64*32*5], sigma_param [4].
    const float* x = nullptr;
    const float* yy = nullptr;
    const float* sp = nullptr;
    for (int i = 0; i < n_in; i++) {
        if (in_sizes[i] == CH - 1) { sp = (const float*)d_in[i]; }
        else if (!x)               { x  = (const float*)d_in[i]; }
        else if (!yy)              { yy = (const float*)d_in[i]; }
    }

    sig_kernel<<<NBLOCKS, THREADS_PER_BLOCK>>>(x, yy, sp, (float*)d_out);
}